// round 14
// baseline (speedup 1.0000x reference)
#include <cuda_runtime.h>
#include <stdint.h>
#include <math.h>

// Dims
#define B_ 128
#define T_ 1024
#define I_ 256
#define H_ 512
#define O_ 256

typedef unsigned long long u64;
typedef ulonglong2 u64x2;

// k-pair interleaved weights: idx = kp2*(ncols*2) + col*2 + kbit
__device__ __align__(16) float gW1i[384 * 1024];  // [kp2][c<512][kb]  k<512:h, k>=512:x
__device__ __align__(16) float gW2i[256 * 1024];  // [kp2][c<512][kb]  (Wih1+Whh1)
__device__ __align__(16) float gW3i[256 * 512];   // [kp2][o<256][kb]  (Wout)

// ---------- helpers ----------
__device__ __forceinline__ u64 pack2(float x, float y) {
    u64 r; asm("mov.b64 %0,{%1,%2};" : "=l"(r) : "f"(x), "f"(y)); return r;
}
__device__ __forceinline__ void unpack2(u64 p, float& x, float& y) {
    asm("mov.b64 {%0,%1},%2;" : "=f"(x), "=f"(y) : "l"(p));
}
__device__ __forceinline__ u64 fma2_(u64 a, u64 b, u64 c) {
    u64 d; asm("fma.rn.f32x2 %0,%1,%2,%3;" : "=l"(d) : "l"(a), "l"(b), "l"(c)); return d;
}
__device__ __forceinline__ u64 add2_(u64 a, u64 b) {
    u64 d; asm("add.rn.f32x2 %0,%1,%2;" : "=l"(d) : "l"(a), "l"(b)); return d;
}
__device__ __forceinline__ float mytanh(float x) {
    float xc = fminf(12.f, fmaxf(-12.f, x));
    float e = __expf(2.f * xc);
    return __fdividef(e - 1.f, e + 1.f);
}
__device__ __forceinline__ void cluster_bar() {
    asm volatile("barrier.cluster.arrive.aligned;" ::: "memory");
    asm volatile("barrier.cluster.wait.aligned;" ::: "memory");
}
__device__ __forceinline__ uint32_t mapa_u32(uint32_t loc, int r) {
    uint32_t rem;
    asm("mapa.shared::cluster.u32 %0, %1, %2;" : "=r"(rem) : "r"(loc), "r"(r));
    return rem;
}
__device__ __forceinline__ void st_async64(uint32_t dst, u64 v, uint32_t mbar) {
    asm volatile("st.async.shared::cluster.mbarrier::complete_tx::bytes.b64 [%0], %1, [%2];"
                 :: "r"(dst), "l"(v), "r"(mbar) : "memory");
}
__device__ __forceinline__ void mbar_init(uint32_t mbar, uint32_t count) {
    asm volatile("mbarrier.init.shared.b64 [%0], %1;" :: "r"(mbar), "r"(count) : "memory");
}
__device__ __forceinline__ void mbar_arm(uint32_t mbar, uint32_t tx) {
    asm volatile("mbarrier.arrive.expect_tx.shared.b64 _, [%0], %1;" :: "r"(mbar), "r"(tx) : "memory");
}
__device__ __forceinline__ void mbar_wait(uint32_t mbar, uint32_t parity) {
    uint32_t done;
    asm volatile(
        "{\n\t.reg .pred p;\n\t"
        "mbarrier.try_wait.parity.acquire.cta.shared::cta.b64 p, [%1], %2;\n\t"
        "selp.b32 %0, 1, 0, p;\n\t}"
        : "=r"(done) : "r"(mbar), "r"(parity) : "memory");
    if (!done) {
        asm volatile(
            "{\n\t.reg .pred P1;\n\t"
            "WAIT_LOOP_%=:\n\t"
            "mbarrier.try_wait.parity.acquire.cta.shared::cta.b64 P1, [%0], %1, 0x989680;\n\t"
            "@P1 bra.uni WAIT_DONE_%=;\n\t"
            "bra.uni WAIT_LOOP_%=;\n\t"
            "WAIT_DONE_%=:\n\t}"
            :: "r"(mbar), "r"(parity) : "memory");
    }
}

// ---------- SMEM layout (float offsets) ----------
// W2S : [0,32768)        Wc slice [kp2][c_local 64][kb]              128 KB
// AST : [32768,38912)    u64[8][384]  per m: kp2 0..255=h2, 256..383=x  24 KB
// ASB : [38912,43008)    u64[8][256]  h1 buffer                      16 KB
// SCR : [43008,51200)    union: SCRA f32[12][512] + SCRC f32[4][256] | SCRB f32[16][512]
// bias: b0s 51200  bcs 51264  bos 51328
// mbar: mbB_lo 51360  mbB_hi 51362  mbA_lo 51364  mbA_hi 51366
#define AST_OFF  32768
#define ASB_OFF  38912
#define SCR_OFF  43008
#define SCRC_REL 6144
#define B0_OFF   51200
#define BC_OFF   51264
#define BO_OFF   51328
#define MBB_LO   51360
#define MBB_HI   51362
#define MBA_LO   51364
#define MBA_HI   51366
#define SMEM_FLOATS 51368
#define SMEM_BYTES (SMEM_FLOATS * 4)
#define TX_HALF 8192u    // 4 ranks x 8m x 64cols x 4B per half exchange

// ---------- prep: build k-pair interleaved weights ----------
__global__ void rnn_prep(const float* __restrict__ Wih0, const float* __restrict__ Whh0,
                         const float* __restrict__ Wih1, const float* __restrict__ Whh1,
                         const float* __restrict__ Wout) {
    int i = blockIdx.x * blockDim.x + threadIdx.x;
    if (i < 384 * 1024) {
        int kp2 = i >> 10, r = i & 1023, c = r >> 1, kb = r & 1;
        int k = 2 * kp2 + kb;
        gW1i[i] = (k < 512) ? Whh0[c * 512 + k] : Wih0[c * 256 + (k - 512)];
    }
    if (i < 256 * 1024) {
        int kp2 = i >> 10, r = i & 1023, c = r >> 1, kb = r & 1;
        int k = 2 * kp2 + kb;
        gW2i[i] = Wih1[c * 512 + k] + Whh1[c * 512 + k];
    }
    if (i < 256 * 512) {
        int kp2 = i >> 9, r = i & 511, o = r >> 1, kb = r & 1;
        int k = 2 * kp2 + kb;
        gW3i[i] = Wout[o * 512 + k];
    }
}

// ---------- main persistent kernel: 1024 threads, 32 warps ----------
// Warp roles: A = ws 0..23 (ksl=ws>>1 in 0..11, m-half=ws&1)
//             C = ws 24..31 (cksl=(ws-24)>>1 in 0..3, m-half=ws&1), runs y(t-1) during A
//             B = all 32 warps (bksl=ws>>1 in 0..15, m-half=ws&1)
__global__ void __launch_bounds__(1024, 1) __cluster_dims__(8, 1, 1)
rnn_main(const float* __restrict__ x, const float* __restrict__ h0,
         const float* __restrict__ bih0, const float* __restrict__ bhh0,
         const float* __restrict__ bih1, const float* __restrict__ bhh1,
         const float* __restrict__ bout, float* __restrict__ out) {
    extern __shared__ float smem[];
    float* W2S  = smem;
    u64*   AST  = reinterpret_cast<u64*>(smem + AST_OFF);   // [m][384]
    float* SCRA = smem + SCR_OFF;                           // 12 x 512
    float* SCRB = smem + SCR_OFF;                           // 16 x 512 (overlay)
    float* SCRC = smem + SCR_OFF + SCRC_REL;                // 4 x 256
    float* b0s = smem + B0_OFF;
    float* bcs = smem + BC_OFF;
    float* bos = smem + BO_OFF;

    const int tid  = threadIdx.x;
    const int lane = tid & 31;
    const int ws   = tid >> 5;
    const int grp8 = (blockIdx.x >> 3) * 8;
    const int rank = blockIdx.x & 7;
    const int nb = rank * 64;
    const int ob = rank * 32;

    uint32_t smem_u32;
    asm("{ .reg .u64 t; cvta.to.shared.u64 t, %1; cvt.u32.u64 %0, t; }"
        : "=r"(smem_u32) : "l"(smem));
    const uint32_t mbBlo = smem_u32 + MBB_LO * 4;
    const uint32_t mbBhi = smem_u32 + MBB_HI * 4;
    const uint32_t mbAlo = smem_u32 + MBA_LO * 4;
    const uint32_t mbAhi = smem_u32 + MBA_HI * 4;

    // ---- biases ----
    if (tid < 64)       b0s[tid] = bih0[nb + tid] + bhh0[nb + tid];
    else if (tid < 128) { int c = tid - 64; bcs[c] = bih1[nb + c] + bhh1[nb + c]; }
    else if (tid < 160) { int c = tid - 128; bos[c] = bout[ob + c]; }

    // ---- W2 slice into SMEM ----
    for (int i = tid; i < 32768; i += 1024) {
        int kp2 = i >> 7, rem = i & 127;
        W2S[i] = gW2i[kp2 * 1024 + rank * 128 + rem];
    }

    // ---- initial staging: h0 + x0 (threads 0..511) ----
    const int sm_ = (tid >> 6) & 7, q = tid & 63;
    if (tid < 512) {
        float4* f4A = reinterpret_cast<float4*>(AST);   // 192 float4 per m
        const float4* hsrc = reinterpret_cast<const float4*>(h0 + (size_t)(grp8 + sm_) * H_);
        f4A[sm_ * 192 + q]      = __ldg(hsrc + q);
        f4A[sm_ * 192 + 64 + q] = __ldg(hsrc + q + 64);
        const float4* xsrc = reinterpret_cast<const float4*>(x + (size_t)(grp8 + sm_) * T_ * I_);
        f4A[sm_ * 192 + 128 + q] = __ldg(xsrc + q);
    }

    if (tid == 0) {
        mbar_init(mbBlo, 1); mbar_init(mbBhi, 1);
        mbar_init(mbAlo, 1); mbar_init(mbAhi, 1);
        mbar_arm(mbBlo, TX_HALF); mbar_arm(mbBhi, TX_HALF);   // for step 0's h1
    }
    __syncthreads();
    cluster_bar();   // once: mbars + SMEM visible cluster-wide

    // ---- role indices & base pointers ----
    const int ksl  = ws >> 1;              // A k-slice 0..11 (valid ws<24)
    const int amh  = (ws & 1) * 4;         // A m-half base
    const int cksl = (ws - 24) >> 1;       // C k-slice 0..3 (valid ws>=24)
    const int cmh  = (ws & 1) * 4;
    const int bksl = ws >> 1;              // B k-slice 0..15
    const int bmh  = (ws & 1) * 4;

    const u64x2* wA = reinterpret_cast<const u64x2*>(gW1i)
                      + (size_t)((ksl < 12 ? ksl : 0) * 32) * 256 + rank * 32 + lane;
    const u64x2* aA = reinterpret_cast<const u64x2*>(AST) + (ksl < 12 ? ksl : 0) * 16;
    const u64*   wC = reinterpret_cast<const u64*>(gW3i)
                      + (size_t)((cksl < 0 ? 0 : cksl) * 64) * 256 + ob + lane;
    const u64x2* aC = reinterpret_cast<const u64x2*>(AST) + (cksl < 0 ? 0 : cksl) * 32;
    // W2S: 32 u64x2 per kp2 row; B slice = 16 kp2 rows  -> bksl * 16 * 32 (FIX)
    const u64x2* wB = reinterpret_cast<const u64x2*>(W2S) + bksl * 16 * 32 + lane;
    const u64x2* aB = reinterpret_cast<const u64x2*>(smem + ASB_OFF) + bksl * 8;

    const int rm = tid >> 5, rc = tid & 31;                    // reducers (tid<256): rm 0..7
    const uint32_t dstB = smem_u32 + (uint32_t)(ASB_OFF * 4) + (uint32_t)((rm * 256 + (nb >> 1) + rc) * 8);
    const uint32_t dstA = smem_u32 + (uint32_t)(AST_OFF * 4) + (uint32_t)((rm * 384 + (nb >> 1) + rc) * 8);
    const uint32_t myMbB = (rank < 4) ? mbBlo : mbBhi;
    const uint32_t myMbA = (rank < 4) ? mbAlo : mbAhi;
    const int em = (tid - 768) >> 5, ec = tid & 31;            // y epilogue (tid>=768)

    for (int t = 0; t <= T_; t++) {
        const int doA = (t < T_), doC = (t > 0);
        const uint32_t pPrev = (uint32_t)((t - 1) & 1);
        const uint32_t pCur  = (uint32_t)(t & 1);

        float4 xr;
        if (doA && tid < 512) {
            int tn = (t + 1 < T_) ? (t + 1) : (T_ - 1);
            xr = __ldg(reinterpret_cast<const float4*>(
                x + ((size_t)(grp8 + sm_) * T_ + tn) * I_) + q);
        }

        // ============ Phase A (warps 0-23) / C(t-1) (warps 24-31) ============
        u64 acc[4][2];   // A/B partials (4 m-rows x 2 col-pairs)
        u64 accc[4];     // C partials
        if (doA && ws < 24) {
            if (t) {
                if (ws < 8)       mbar_wait(mbAlo, pPrev);
                else if (ws < 16) mbar_wait(mbAhi, pPrev);
                // ws 16-23: x region, no wait
            }
#pragma unroll
            for (int mi = 0; mi < 4; mi++) { acc[mi][0] = 0; acc[mi][1] = 0; }
            u64x2 pw0 = wA[0], pw1 = wA[256];
#pragma unroll 4
            for (int blk = 0; blk < 16; blk++) {
                u64x2 w0 = pw0, w1 = pw1;
                if (blk < 15) {
                    pw0 = wA[(size_t)(2 * blk + 2) * 256];
                    pw1 = wA[(size_t)(2 * blk + 3) * 256];
                }
#pragma unroll
                for (int mi = 0; mi < 4; mi++) {
                    u64x2 a2 = aA[(amh + mi) * 192 + blk];
                    acc[mi][0] = fma2_(a2.x, w0.x, acc[mi][0]);
                    acc[mi][1] = fma2_(a2.x, w0.y, acc[mi][1]);
                    acc[mi][0] = fma2_(a2.y, w1.x, acc[mi][0]);
                    acc[mi][1] = fma2_(a2.y, w1.y, acc[mi][1]);
                }
            }
        } else if (ws >= 24 && doC) {
            mbar_wait(mbAlo, pPrev);
            mbar_wait(mbAhi, pPrev);
#pragma unroll
            for (int mi = 0; mi < 4; mi++) accc[mi] = 0;
            u64 pc0 = wC[0], pc1 = wC[256];
#pragma unroll 4
            for (int blk = 0; blk < 32; blk++) {
                u64 w0 = pc0, w1 = pc1;
                if (blk < 31) {
                    pc0 = wC[(size_t)(2 * blk + 2) * 256];
                    pc1 = wC[(size_t)(2 * blk + 3) * 256];
                }
#pragma unroll
                for (int mi = 0; mi < 4; mi++) {
                    u64x2 a2 = aC[(cmh + mi) * 192 + blk];
                    accc[mi] = fma2_(a2.x, w0, accc[mi]);
                    accc[mi] = fma2_(a2.y, w1, accc[mi]);
                }
            }
        }
        __syncthreads();  // (a): AST reads done; prev-step SCR readers done

        if (doA && ws < 24) {        // A-combine -> SCRA
#pragma unroll
            for (int mi = 0; mi < 4; mi++) {
                float e0, o0, e1, o1;
                unpack2(acc[mi][0], e0, o0); unpack2(acc[mi][1], e1, o1);
                *reinterpret_cast<float2*>(&SCRA[ksl * 512 + (amh + mi) * 64 + 2 * lane]) =
                    make_float2(e0 + o0, e1 + o1);
            }
        } else if (ws >= 24 && doC) { // C-combine -> SCRC
#pragma unroll
            for (int mi = 0; mi < 4; mi++) {
                float e, o; unpack2(accc[mi], e, o);
                SCRC[cksl * 256 + (cmh + mi) * 32 + lane] = e + o;
            }
        }
        if (doA) {
            if (tid < 512)
                reinterpret_cast<float4*>(AST)[sm_ * 192 + 128 + q] = xr;   // stage x_{t+1}
            if (tid == 0) { mbar_arm(mbAlo, TX_HALF); mbar_arm(mbAhi, TX_HALF); }
        }
        __syncthreads();  // (b)

        if (doC && tid >= 768) {      // y(t-1) epilogue
            float s = SCRC[em * 32 + ec] + SCRC[256 + em * 32 + ec]
                    + SCRC[512 + em * 32 + ec] + SCRC[768 + em * 32 + ec] + bos[ec];
            out[(size_t)(grp8 + em) * (T_ * O_) + (size_t)(t - 1) * O_ + ob + ec] = s;
        }
        if (!doA) break;

        if (tid < 256) {              // h1-reduce (12-way) + tanh + publish halves
            const float* base = SCRA + rm * 64 + 2 * rc;
            u64 s = *reinterpret_cast<const u64*>(base);
#pragma unroll
            for (int w2 = 1; w2 < 12; w2++)
                s = add2_(s, *reinterpret_cast<const u64*>(base + w2 * 512));
            s = add2_(s, *reinterpret_cast<const u64*>(b0s + 2 * rc));
            float e, o; unpack2(s, e, o);
            u64 v = pack2(mytanh(e), mytanh(o));
#pragma unroll
            for (int r = 0; r < 8; r++)
                st_async64(mapa_u32(dstB, r), v, mapa_u32(myMbB, r));
        }

        // ============ Phase B: h2 = tanh(h1 @ Wc^T + bc), all 32 warps ============
        if (ws < 16) mbar_wait(mbBlo, pCur); else mbar_wait(mbBhi, pCur);
#pragma unroll
        for (int mi = 0; mi < 4; mi++) { acc[mi][0] = 0; acc[mi][1] = 0; }
#pragma unroll
        for (int blk = 0; blk < 8; blk++) {
            u64x2 w0 = wB[(2 * blk) * 32];
            u64x2 w1 = wB[(2 * blk + 1) * 32];
#pragma unroll
            for (int mi = 0; mi < 4; mi++) {
                u64x2 a2 = aB[(bmh + mi) * 128 + blk];
                acc[mi][0] = fma2_(a2.x, w0.x, acc[mi][0]);
                acc[mi][1] = fma2_(a2.x, w0.y, acc[mi][1]);
                acc[mi][0] = fma2_(a2.y, w1.x, acc[mi][0]);
                acc[mi][1] = fma2_(a2.y, w1.y, acc[mi][1]);
            }
        }
        __syncthreads();  // (c): SCRA/SCRC readers done; safe to overlay SCRB
#pragma unroll
        for (int mi = 0; mi < 4; mi++) {
            float e0, o0, e1, o1;
            unpack2(acc[mi][0], e0, o0); unpack2(acc[mi][1], e1, o1);
            *reinterpret_cast<float2*>(&SCRB[bksl * 512 + (bmh + mi) * 64 + 2 * lane]) =
                make_float2(e0 + o0, e1 + o1);
        }
        if (tid == 0) { mbar_arm(mbBlo, TX_HALF); mbar_arm(mbBhi, TX_HALF); }  // for t+1
        __syncthreads();  // (d)

        if (tid < 256) {              // h2-reduce (16-way) + tanh + publish halves
            const float* base = SCRB + rm * 64 + 2 * rc;
            u64 s = *reinterpret_cast<const u64*>(base);
#pragma unroll
            for (int w2 = 1; w2 < 16; w2++)
                s = add2_(s, *reinterpret_cast<const u64*>(base + w2 * 512));
            s = add2_(s, *reinterpret_cast<const u64*>(bcs + 2 * rc));
            float e, o; unpack2(s, e, o);
            u64 v = pack2(mytanh(e), mytanh(o));
#pragma unroll
            for (int r = 0; r < 8; r++)
                st_async64(mapa_u32(dstA, r), v, mapa_u32(myMbA, r));
        }
    }
    cluster_bar();  // keep SMEM alive until all cluster traffic retired
}

extern "C" void kernel_launch(void* const* d_in, const int* in_sizes, int n_in,
                              void* d_out, int out_size) {
    const float* x    = (const float*)d_in[0];
    const float* h0   = (const float*)d_in[1];
    const float* Wih0 = (const float*)d_in[2];
    const float* bih0 = (const float*)d_in[3];
    const float* Whh0 = (const float*)d_in[4];
    const float* bhh0 = (const float*)d_in[5];
    const float* Wih1 = (const float*)d_in[6];
    const float* bih1 = (const float*)d_in[7];
    const float* Whh1 = (const float*)d_in[8];
    const float* bhh1 = (const float*)d_in[9];
    const float* Wout = (const float*)d_in[10];
    const float* bout = (const float*)d_in[11];
    float* out = (float*)d_out;

    cudaFuncSetAttribute(rnn_main, cudaFuncAttributeMaxDynamicSharedMemorySize, SMEM_BYTES);

    rnn_prep<<<1536, 256>>>(Wih0, Whh0, Wih1, Whh1, Wout);
    rnn_main<<<128, 1024, SMEM_BYTES>>>(x, h0, bih0, bhh0, bih1, bhh1, bout, out);
}

// round 15
// speedup vs baseline: 1.5083x; 1.5083x over previous
#include <cuda_runtime.h>
#include <stdint.h>
#include <math.h>

// Dims
#define B_ 128
#define T_ 1024
#define I_ 256
#define H_ 512
#define O_ 256

typedef unsigned long long u64;
typedef ulonglong2 u64x2;

// k-pair interleaved weights: idx = kp2*(ncols*2) + col*2 + kbit
__device__ __align__(16) float gW1i[384 * 1024];  // [kp2][c<512][kb]  k<512:h(Whh0), k>=512:x(Wih0)
__device__ __align__(16) float gW2i[256 * 1024];  // [kp2][c<512][kb]  (Wih1+Whh1)
__device__ __align__(16) float gW3i[256 * 512];   // [kp2][o<256][kb]  (Wout)
// big scratch: x-projection and h2 history
__device__ float gXP[(size_t)T_ * B_ * H_];       // [t][b][c]  256MB
__device__ float gH2[(size_t)B_ * T_ * H_];       // [b][t][c]  256MB

// ---------- helpers ----------
__device__ __forceinline__ u64 pack2(float x, float y) {
    u64 r; asm("mov.b64 %0,{%1,%2};" : "=l"(r) : "f"(x), "f"(y)); return r;
}
__device__ __forceinline__ void unpack2(u64 p, float& x, float& y) {
    asm("mov.b64 {%0,%1},%2;" : "=f"(x), "=f"(y) : "l"(p));
}
__device__ __forceinline__ u64 fma2_(u64 a, u64 b, u64 c) {
    u64 d; asm("fma.rn.f32x2 %0,%1,%2,%3;" : "=l"(d) : "l"(a), "l"(b), "l"(c)); return d;
}
__device__ __forceinline__ u64 add2_(u64 a, u64 b) {
    u64 d; asm("add.rn.f32x2 %0,%1,%2;" : "=l"(d) : "l"(a), "l"(b)); return d;
}
__device__ __forceinline__ float mytanh(float x) {
    float xc = fminf(12.f, fmaxf(-12.f, x));
    float e = __expf(2.f * xc);
    return __fdividef(e - 1.f, e + 1.f);
}
__device__ __forceinline__ void cluster_bar() {
    asm volatile("barrier.cluster.arrive.aligned;" ::: "memory");
    asm volatile("barrier.cluster.wait.aligned;" ::: "memory");
}
__device__ __forceinline__ uint32_t mapa_u32(uint32_t loc, int r) {
    uint32_t rem;
    asm("mapa.shared::cluster.u32 %0, %1, %2;" : "=r"(rem) : "r"(loc), "r"(r));
    return rem;
}
__device__ __forceinline__ void st_async64(uint32_t dst, u64 v, uint32_t mbar) {
    asm volatile("st.async.shared::cluster.mbarrier::complete_tx::bytes.b64 [%0], %1, [%2];"
                 :: "r"(dst), "l"(v), "r"(mbar) : "memory");
}
__device__ __forceinline__ void mbar_init(uint32_t mbar, uint32_t count) {
    asm volatile("mbarrier.init.shared.b64 [%0], %1;" :: "r"(mbar), "r"(count) : "memory");
}
__device__ __forceinline__ void mbar_arm(uint32_t mbar, uint32_t tx) {
    asm volatile("mbarrier.arrive.expect_tx.shared.b64 _, [%0], %1;" :: "r"(mbar), "r"(tx) : "memory");
}
__device__ __forceinline__ void mbar_wait(uint32_t mbar, uint32_t parity) {
    uint32_t done;
    asm volatile(
        "{\n\t.reg .pred p;\n\t"
        "mbarrier.try_wait.parity.acquire.cta.shared::cta.b64 p, [%1], %2;\n\t"
        "selp.b32 %0, 1, 0, p;\n\t}"
        : "=r"(done) : "r"(mbar), "r"(parity) : "memory");
    if (!done) {
        asm volatile(
            "{\n\t.reg .pred P1;\n\t"
            "WAIT_LOOP_%=:\n\t"
            "mbarrier.try_wait.parity.acquire.cta.shared::cta.b64 P1, [%0], %1, 0x989680;\n\t"
            "@P1 bra.uni WAIT_DONE_%=;\n\t"
            "bra.uni WAIT_LOOP_%=;\n\t"
            "WAIT_DONE_%=:\n\t}"
            :: "r"(mbar), "r"(parity) : "memory");
    }
}

// ---------- prep: build k-pair interleaved weights ----------
__global__ void rnn_prep(const float* __restrict__ Wih0, const float* __restrict__ Whh0,
                         const float* __restrict__ Wih1, const float* __restrict__ Whh1,
                         const float* __restrict__ Wout) {
    int i = blockIdx.x * blockDim.x + threadIdx.x;
    if (i < 384 * 1024) {
        int kp2 = i >> 10, r = i & 1023, c = r >> 1, kb = r & 1;
        int k = 2 * kp2 + kb;
        gW1i[i] = (k < 512) ? Whh0[c * 512 + k] : Wih0[c * 256 + (k - 512)];
    }
    if (i < 256 * 1024) {
        int kp2 = i >> 10, r = i & 1023, c = r >> 1, kb = r & 1;
        int k = 2 * kp2 + kb;
        gW2i[i] = Wih1[c * 512 + k] + Whh1[c * 512 + k];
    }
    if (i < 256 * 512) {
        int kp2 = i >> 9, r = i & 511, o = r >> 1, kb = r & 1;
        int k = 2 * kp2 + kb;
        gW3i[i] = Wout[o * 512 + k];
    }
}

// ---------- pass 1: XP[t][b][c] = x[b][t][:] @ Wih0^T + (bih0+bhh0) ----------
// grid = 1024 t x 4 m-groups(32); block 1024 = 32 warps = 8 col-slices x 4 m-octs
__global__ void __launch_bounds__(1024, 1)
rnn_xproj(const float* __restrict__ x, const float* __restrict__ bih0,
          const float* __restrict__ bhh0) {
    extern __shared__ float sm1[];   // xs: [32][128 u64]=8192 f, b0s: 512 f
    float* b0s = sm1 + 8192;
    const int tid = threadIdx.x, lane = tid & 31, ws = tid >> 5;
    const int t = blockIdx.x >> 2, grp32 = (blockIdx.x & 3) * 32;

    if (tid < 512) b0s[tid] = bih0[tid] + bhh0[tid];
    {   // stage x: 32 m x 64 float4
        float4* xs4 = reinterpret_cast<float4*>(sm1);
        const float4* xf4 = reinterpret_cast<const float4*>(x);
#pragma unroll
        for (int k2 = 0; k2 < 2; k2++) {
            int j = tid + k2 * 1024;
            int m = j >> 6, q = j & 63;
            xs4[m * 64 + q] = __ldg(&xf4[((size_t)(grp32 + m) * T_ + t) * 64 + q]);
        }
    }
    __syncthreads();

    const int s = ws & 7, o = ws >> 3;
    const u64x2* wp = reinterpret_cast<const u64x2*>(gW1i) + (size_t)256 * 256 + s * 32 + lane;
    const u64x2* ax = reinterpret_cast<const u64x2*>(sm1) + (o * 8) * 64;

    u64 acc[8][2];
#pragma unroll
    for (int mi = 0; mi < 8; mi++) { acc[mi][0] = 0; acc[mi][1] = 0; }
    u64x2 pw0 = wp[0], pw1 = wp[256];
#pragma unroll 4
    for (int blk = 0; blk < 64; blk++) {
        u64x2 w0 = pw0, w1 = pw1;
        if (blk < 63) { pw0 = wp[(size_t)(2 * blk + 2) * 256]; pw1 = wp[(size_t)(2 * blk + 3) * 256]; }
#pragma unroll
        for (int mi = 0; mi < 8; mi++) {
            u64x2 a2 = ax[mi * 64 + blk];
            acc[mi][0] = fma2_(a2.x, w0.x, acc[mi][0]);
            acc[mi][1] = fma2_(a2.x, w0.y, acc[mi][1]);
            acc[mi][0] = fma2_(a2.y, w1.x, acc[mi][0]);
            acc[mi][1] = fma2_(a2.y, w1.y, acc[mi][1]);
        }
    }
    const int c0 = s * 64 + 2 * lane;
    float2 bb = *reinterpret_cast<const float2*>(&b0s[c0]);
#pragma unroll
    for (int mi = 0; mi < 8; mi++) {
        float e0, o0, e1, o1;
        unpack2(acc[mi][0], e0, o0); unpack2(acc[mi][1], e1, o1);
        *reinterpret_cast<float2*>(
            &gXP[((size_t)t * 128 + grp32 + o * 8 + mi) * 512 + c0]) =
            make_float2(e0 + o0 + bb.x, e1 + o1 + bb.y);
    }
}

// ---------- pass 3: Y = H2 @ Wout^T + bout ----------
// grid = BT/32; block 512 = 16 warps = 4 col-slices(64) x 4 m-octs; K=512
__global__ void __launch_bounds__(512, 1)
rnn_yproj(const float* __restrict__ bout, float* __restrict__ out) {
    extern __shared__ float sm3[];   // hs: [32][256 u64]=16384 f, bos: 256 f
    float* bos = sm3 + 16384;
    const int tid = threadIdx.x, lane = tid & 31, ws = tid >> 5;
    const size_t r0 = (size_t)blockIdx.x * 32;

    if (tid < 256) bos[tid] = bout[tid];
    {   // stage H2 rows: 32 x 128 float4
        float4* hs4 = reinterpret_cast<float4*>(sm3);
        const float4* hf4 = reinterpret_cast<const float4*>(gH2);
#pragma unroll
        for (int k2 = 0; k2 < 8; k2++) {
            int j = tid + k2 * 512;
            int m = j >> 7, q = j & 127;
            hs4[m * 128 + q] = __ldg(&hf4[(r0 + m) * 128 + q]);
        }
    }
    __syncthreads();

    const int s = ws & 3, o = ws >> 2;
    const u64x2* wp = reinterpret_cast<const u64x2*>(gW3i) + s * 32 + lane;   // row=128 u64x2
    const u64x2* ah = reinterpret_cast<const u64x2*>(sm3) + (o * 8) * 128;

    u64 acc[8][2];
#pragma unroll
    for (int mi = 0; mi < 8; mi++) { acc[mi][0] = 0; acc[mi][1] = 0; }
    u64x2 pw0 = wp[0], pw1 = wp[128];
#pragma unroll 4
    for (int blk = 0; blk < 128; blk++) {
        u64x2 w0 = pw0, w1 = pw1;
        if (blk < 127) { pw0 = wp[(size_t)(2 * blk + 2) * 128]; pw1 = wp[(size_t)(2 * blk + 3) * 128]; }
#pragma unroll
        for (int mi = 0; mi < 8; mi++) {
            u64x2 a2 = ah[mi * 128 + blk];
            acc[mi][0] = fma2_(a2.x, w0.x, acc[mi][0]);
            acc[mi][1] = fma2_(a2.x, w0.y, acc[mi][1]);
            acc[mi][0] = fma2_(a2.y, w1.x, acc[mi][0]);
            acc[mi][1] = fma2_(a2.y, w1.y, acc[mi][1]);
        }
    }
    const int c0 = s * 64 + 2 * lane;
    float2 bb = *reinterpret_cast<const float2*>(&bos[c0]);
#pragma unroll
    for (int mi = 0; mi < 8; mi++) {
        float e0, o0, e1, o1;
        unpack2(acc[mi][0], e0, o0); unpack2(acc[mi][1], e1, o1);
        *reinterpret_cast<float2*>(&out[(r0 + o * 8 + mi) * 256 + c0]) =
            make_float2(e0 + o0 + bb.x, e1 + o1 + bb.y);
    }
}

// ---------- pass 2 SMEM layout (float offsets) ----------
// W2S 0..32768 | AST 32768..36864 u64[8][256] | ASB 36864..40960 u64[8][256]
// SCR 40960..49152 f32[16][512] | bcs 49152..49216 | mbars 49216..49224
#define AST_OFF  32768
#define ASB_OFF  36864
#define SCR_OFF  40960
#define BC_OFF   49152
#define MBB_LO   49216
#define MBB_HI   49218
#define MBA_LO   49220
#define MBA_HI   49222
#define SMEM_FLOATS 49224
#define SMEM_BYTES (SMEM_FLOATS * 4)
#define TX_HALF 8192u

// ---------- pass 2: recurrent core (cluster 8, 512 threads, 16 warps) ----------
__global__ void __launch_bounds__(512, 1) __cluster_dims__(8, 1, 1)
rnn_main2(const float* __restrict__ h0, const float* __restrict__ bih1,
          const float* __restrict__ bhh1) {
    extern __shared__ float smem[];
    float* W2S = smem;
    u64*   AST = reinterpret_cast<u64*>(smem + AST_OFF);
    float* SCR = smem + SCR_OFF;
    float* bcs = smem + BC_OFF;

    const int tid  = threadIdx.x;
    const int lane = tid & 31;
    const int ws   = tid >> 5;   // 16-way split-K slice
    const int grp8 = (blockIdx.x >> 3) * 8;
    const int rank = blockIdx.x & 7;
    const int nb = rank * 64;

    uint32_t smem_u32;
    asm("{ .reg .u64 t; cvta.to.shared.u64 t, %1; cvt.u32.u64 %0, t; }"
        : "=r"(smem_u32) : "l"(smem));
    const uint32_t mbBlo = smem_u32 + MBB_LO * 4;
    const uint32_t mbBhi = smem_u32 + MBB_HI * 4;
    const uint32_t mbAlo = smem_u32 + MBA_LO * 4;
    const uint32_t mbAhi = smem_u32 + MBA_HI * 4;

    if (tid < 64) bcs[tid] = bih1[nb + tid] + bhh1[nb + tid];

    for (int i = tid; i < 32768; i += 512) {
        int kp2 = i >> 7, rem = i & 127;
        W2S[i] = gW2i[kp2 * 1024 + rank * 128 + rem];
    }
    {   // stage h0 full row per m
        const int m = tid >> 6, q = tid & 63;
        float4* f4 = reinterpret_cast<float4*>(AST);
        const float4* hsrc = reinterpret_cast<const float4*>(h0 + (size_t)(grp8 + m) * H_);
        f4[m * 128 + q]      = __ldg(hsrc + q);
        f4[m * 128 + 64 + q] = __ldg(hsrc + q + 64);
    }
    if (tid == 0) {
        mbar_init(mbBlo, 1); mbar_init(mbBhi, 1);
        mbar_init(mbAlo, 1); mbar_init(mbAhi, 1);
        mbar_arm(mbBlo, TX_HALF); mbar_arm(mbBhi, TX_HALF);
    }
    __syncthreads();
    cluster_bar();

    // base pointers
    const u64x2* wA = reinterpret_cast<const u64x2*>(gW1i) + (size_t)(ws * 16) * 256 + rank * 32 + lane;
    const u64x2* aA = reinterpret_cast<const u64x2*>(AST) + ws * 8;                 // + m*128 + blk
    const u64x2* wB = reinterpret_cast<const u64x2*>(W2S) + ws * 16 * 32 + lane;    // 32 u64x2/kp2
    const u64x2* aB = reinterpret_cast<const u64x2*>(smem + ASB_OFF) + ws * 8;

    const int rm = tid >> 5, rc = tid & 31;   // reducers (tid<256)
    const uint32_t dstB = smem_u32 + (uint32_t)(ASB_OFF * 4) + (uint32_t)((rm * 256 + (nb >> 1) + rc) * 8);
    const uint32_t dstA = smem_u32 + (uint32_t)(AST_OFF * 4) + (uint32_t)((rm * 384 / 384 * 256 + (nb >> 1) + rc) * 8);
    const uint32_t myMbB = (rank < 4) ? mbBlo : mbBhi;
    const uint32_t myMbA = (rank < 4) ? mbAlo : mbAhi;
    const size_t xoff = (size_t)(grp8 + rm) * 512 + nb + 2 * rc;       // + t*65536
    const size_t hoff = (size_t)(grp8 + rm) * T_ * 512 + nb + 2 * rc;  // + t*512

    for (int t = 0; t < T_; t++) {
        const uint32_t pPrev = (uint32_t)((t - 1) & 1);
        const uint32_t pCur  = (uint32_t)(t & 1);

        u64 xp_r = 0;
        if (tid < 256)
            xp_r = *reinterpret_cast<const u64*>(gXP + (size_t)t * 65536 + xoff);

        // ===== Phase A: h1 = tanh(h2 @ Whh0^T + XP[t]) =====
        u64x2 pw0 = wA[0], pw1 = wA[256];   // prime before wait (independent of exchange)
        if (t) { if (ws < 8) mbar_wait(mbAlo, pPrev); else mbar_wait(mbAhi, pPrev); }
        u64 acc[8][2];
#pragma unroll
        for (int m = 0; m < 8; m++) { acc[m][0] = 0; acc[m][1] = 0; }
#pragma unroll
        for (int blk = 0; blk < 8; blk++) {
            u64x2 w0 = pw0, w1 = pw1;
            if (blk < 7) { pw0 = wA[(size_t)(2 * blk + 2) * 256]; pw1 = wA[(size_t)(2 * blk + 3) * 256]; }
#pragma unroll
            for (int m = 0; m < 8; m++) {
                u64x2 a2 = aA[m * 128 + blk];
                acc[m][0] = fma2_(a2.x, w0.x, acc[m][0]);
                acc[m][1] = fma2_(a2.x, w0.y, acc[m][1]);
                acc[m][0] = fma2_(a2.y, w1.x, acc[m][0]);
                acc[m][1] = fma2_(a2.y, w1.y, acc[m][1]);
            }
        }
        __syncthreads();  // (a): AST reads done; prev SCR readers done
#pragma unroll
        for (int m = 0; m < 8; m++) {
            float e0, o0, e1, o1;
            unpack2(acc[m][0], e0, o0); unpack2(acc[m][1], e1, o1);
            *reinterpret_cast<float2*>(&SCR[ws * 512 + m * 64 + 2 * lane]) =
                make_float2(e0 + o0, e1 + o1);
        }
        if (tid == 0) { mbar_arm(mbAlo, TX_HALF); mbar_arm(mbAhi, TX_HALF); }
        __syncthreads();  // (b)
        if (tid < 256) {  // reduce 16-way + XP + tanh -> publish h1 halves
            const float* base = SCR + rm * 64 + 2 * rc;
            u64 s = *reinterpret_cast<const u64*>(base);
#pragma unroll
            for (int w2 = 1; w2 < 16; w2++)
                s = add2_(s, *reinterpret_cast<const u64*>(base + w2 * 512));
            s = add2_(s, xp_r);
            float e, o; unpack2(s, e, o);
            u64 v = pack2(mytanh(e), mytanh(o));
#pragma unroll
            for (int r = 0; r < 8; r++)
                st_async64(mapa_u32(dstB, r), v, mapa_u32(myMbB, r));
        }

        // ===== Phase B: h2 = tanh(h1 @ Wc^T + bc) =====
        if (ws < 8) mbar_wait(mbBlo, pCur); else mbar_wait(mbBhi, pCur);
#pragma unroll
        for (int m = 0; m < 8; m++) { acc[m][0] = 0; acc[m][1] = 0; }
#pragma unroll
        for (int blk = 0; blk < 8; blk++) {
            u64x2 w0 = wB[(2 * blk) * 32];
            u64x2 w1 = wB[(2 * blk + 1) * 32];
#pragma unroll
            for (int m = 0; m < 8; m++) {
                u64x2 a2 = aB[m * 128 + blk];
                acc[m][0] = fma2_(a2.x, w0.x, acc[m][0]);
                acc[m][1] = fma2_(a2.x, w0.y, acc[m][1]);
                acc[m][0] = fma2_(a2.y, w1.x, acc[m][0]);
                acc[m][1] = fma2_(a2.y, w1.y, acc[m][1]);
            }
        }
        __syncthreads();  // (c): SCR readers (h1-reduce) done
#pragma unroll
        for (int m = 0; m < 8; m++) {
            float e0, o0, e1, o1;
            unpack2(acc[m][0], e0, o0); unpack2(acc[m][1], e1, o1);
            *reinterpret_cast<float2*>(&SCR[ws * 512 + m * 64 + 2 * lane]) =
                make_float2(e0 + o0, e1 + o1);
        }
        if (tid == 0) { mbar_arm(mbBlo, TX_HALF); mbar_arm(mbBhi, TX_HALF); }  // for t+1
        __syncthreads();  // (d)
        if (tid < 256) {  // reduce + tanh -> publish h2 + store H2
            const float* base = SCR + rm * 64 + 2 * rc;
            u64 s = *reinterpret_cast<const u64*>(base);
#pragma unroll
            for (int w2 = 1; w2 < 16; w2++)
                s = add2_(s, *reinterpret_cast<const u64*>(base + w2 * 512));
            s = add2_(s, *reinterpret_cast<const u64*>(bcs + 2 * rc));
            float e, o; unpack2(s, e, o);
            u64 v = pack2(mytanh(e), mytanh(o));
#pragma unroll
            for (int r = 0; r < 8; r++)
                st_async64(mapa_u32(dstA, r), v, mapa_u32(myMbA, r));
            *reinterpret_cast<u64*>(&gH2[hoff + (size_t)t * 512]) = v;
        }
    }
    // drain final h2 exchange, then keep SMEM alive until cluster traffic retires
    mbar_wait(mbAlo, (uint32_t)((T_ - 1) & 1));
    mbar_wait(mbAhi, (uint32_t)((T_ - 1) & 1));
    cluster_bar();
}

extern "C" void kernel_launch(void* const* d_in, const int* in_sizes, int n_in,
                              void* d_out, int out_size) {
    const float* x    = (const float*)d_in[0];
    const float* h0   = (const float*)d_in[1];
    const float* Wih0 = (const float*)d_in[2];
    const float* bih0 = (const float*)d_in[3];
    const float* Whh0 = (const float*)d_in[4];
    const float* bhh0 = (const float*)d_in[5];
    const float* Wih1 = (const float*)d_in[6];
    const float* bih1 = (const float*)d_in[7];
    const float* Whh1 = (const float*)d_in[8];
    const float* bhh1 = (const float*)d_in[9];
    const float* Wout = (const float*)d_in[10];
    const float* bout = (const float*)d_in[11];
    float* out = (float*)d_out;

    cudaFuncSetAttribute(rnn_main2, cudaFuncAttributeMaxDynamicSharedMemorySize, SMEM_BYTES);
    cudaFuncSetAttribute(rnn_yproj, cudaFuncAttributeMaxDynamicSharedMemorySize, (16384 + 256) * 4);

    rnn_prep<<<1536, 256>>>(Wih0, Whh0, Wih1, Whh1, Wout);
    rnn_xproj<<<4096, 1024, (8192 + 512) * 4>>>(x, bih0, bhh0);
    rnn_main2<<<128, 512, SMEM_BYTES>>>(h0, bih1, bhh1);
    rnn_yproj<<<4096, 512, (16384 + 256) * 4>>>(bout, out);
}

// round 16
// speedup vs baseline: 1.5235x; 1.0101x over previous
#include <cuda_runtime.h>
#include <stdint.h>
#include <math.h>

// Dims
#define B_ 128
#define T_ 1024
#define I_ 256
#define H_ 512
#define O_ 256

typedef unsigned long long u64;
typedef ulonglong2 u64x2;

// k-pair interleaved weights: idx = kp2*(ncols*2) + col*2 + kbit
__device__ __align__(16) float gW1i[384 * 1024];  // [kp2][c<512][kb]  k<512:h(Whh0), k>=512:x(Wih0)
__device__ __align__(16) float gW2i[256 * 1024];  // [kp2][c<512][kb]  (Wih1+Whh1)
__device__ __align__(16) float gW3i[256 * 512];   // [kp2][o<256][kb]  (Wout)
// big scratch: x-projection and h2 history
__device__ float gXP[(size_t)T_ * B_ * H_];       // [t][b][c]
__device__ float gH2[(size_t)B_ * T_ * H_];       // [b][t][c]

// ---------- helpers ----------
__device__ __forceinline__ u64 pack2(float x, float y) {
    u64 r; asm("mov.b64 %0,{%1,%2};" : "=l"(r) : "f"(x), "f"(y)); return r;
}
__device__ __forceinline__ void unpack2(u64 p, float& x, float& y) {
    asm("mov.b64 {%0,%1},%2;" : "=f"(x), "=f"(y) : "l"(p));
}
__device__ __forceinline__ u64 fma2_(u64 a, u64 b, u64 c) {
    u64 d; asm("fma.rn.f32x2 %0,%1,%2,%3;" : "=l"(d) : "l"(a), "l"(b), "l"(c)); return d;
}
__device__ __forceinline__ u64 add2_(u64 a, u64 b) {
    u64 d; asm("add.rn.f32x2 %0,%1,%2;" : "=l"(d) : "l"(a), "l"(b)); return d;
}
__device__ __forceinline__ float mytanh(float x) {
    float xc = fminf(12.f, fmaxf(-12.f, x));
    float e = __expf(2.f * xc);
    return __fdividef(e - 1.f, e + 1.f);
}
__device__ __forceinline__ void cluster_bar() {
    asm volatile("barrier.cluster.arrive.aligned;" ::: "memory");
    asm volatile("barrier.cluster.wait.aligned;" ::: "memory");
}
__device__ __forceinline__ uint32_t mapa_u32(uint32_t loc, int r) {
    uint32_t rem;
    asm("mapa.shared::cluster.u32 %0, %1, %2;" : "=r"(rem) : "r"(loc), "r"(r));
    return rem;
}
__device__ __forceinline__ void st_async64(uint32_t dst, u64 v, uint32_t mbar) {
    asm volatile("st.async.shared::cluster.mbarrier::complete_tx::bytes.b64 [%0], %1, [%2];"
                 :: "r"(dst), "l"(v), "r"(mbar) : "memory");
}
__device__ __forceinline__ void mbar_init(uint32_t mbar, uint32_t count) {
    asm volatile("mbarrier.init.shared.b64 [%0], %1;" :: "r"(mbar), "r"(count) : "memory");
}
__device__ __forceinline__ void mbar_arm(uint32_t mbar, uint32_t tx) {
    asm volatile("mbarrier.arrive.expect_tx.shared.b64 _, [%0], %1;" :: "r"(mbar), "r"(tx) : "memory");
}
__device__ __forceinline__ void mbar_wait(uint32_t mbar, uint32_t parity) {
    uint32_t done;
    asm volatile(
        "{\n\t.reg .pred p;\n\t"
        "mbarrier.try_wait.parity.acquire.cta.shared::cta.b64 p, [%1], %2;\n\t"
        "selp.b32 %0, 1, 0, p;\n\t}"
        : "=r"(done) : "r"(mbar), "r"(parity) : "memory");
    if (!done) {
        asm volatile(
            "{\n\t.reg .pred P1;\n\t"
            "WAIT_LOOP_%=:\n\t"
            "mbarrier.try_wait.parity.acquire.cta.shared::cta.b64 P1, [%0], %1, 0x989680;\n\t"
            "@P1 bra.uni WAIT_DONE_%=;\n\t"
            "bra.uni WAIT_LOOP_%=;\n\t"
            "WAIT_DONE_%=:\n\t}"
            :: "r"(mbar), "r"(parity) : "memory");
    }
}
// 16-way tree reduce of u64 f32x2 partials at stride (floats)
__device__ __forceinline__ u64 tree_reduce16(const float* base, int stride_f) {
    u64 v[16];
#pragma unroll
    for (int w2 = 0; w2 < 16; w2++)
        v[w2] = *reinterpret_cast<const u64*>(base + w2 * stride_f);
#pragma unroll
    for (int st = 1; st < 16; st <<= 1)
#pragma unroll
        for (int i = 0; i < 16; i += 2 * st)
            v[i] = add2_(v[i], v[i + st]);
    return v[0];
}

// ---------- prep: build k-pair interleaved weights ----------
__global__ void rnn_prep(const float* __restrict__ Wih0, const float* __restrict__ Whh0,
                         const float* __restrict__ Wih1, const float* __restrict__ Whh1,
                         const float* __restrict__ Wout) {
    int i = blockIdx.x * blockDim.x + threadIdx.x;
    if (i < 384 * 1024) {
        int kp2 = i >> 10, r = i & 1023, c = r >> 1, kb = r & 1;
        int k = 2 * kp2 + kb;
        gW1i[i] = (k < 512) ? Whh0[c * 512 + k] : Wih0[c * 256 + (k - 512)];
    }
    if (i < 256 * 1024) {
        int kp2 = i >> 10, r = i & 1023, c = r >> 1, kb = r & 1;
        int k = 2 * kp2 + kb;
        gW2i[i] = Wih1[c * 512 + k] + Whh1[c * 512 + k];
    }
    if (i < 256 * 512) {
        int kp2 = i >> 9, r = i & 511, o = r >> 1, kb = r & 1;
        int k = 2 * kp2 + kb;
        gW3i[i] = Wout[o * 512 + k];
    }
}

// ---------- pass 1: XP[t][b][c] = x[b][t][:] @ Wih0^T + (bih0+bhh0) ----------
__global__ void __launch_bounds__(1024, 1)
rnn_xproj(const float* __restrict__ x, const float* __restrict__ bih0,
          const float* __restrict__ bhh0) {
    extern __shared__ float sm1[];   // xs: 8192 f, b0s: 512 f
    float* b0s = sm1 + 8192;
    const int tid = threadIdx.x, lane = tid & 31, ws = tid >> 5;
    const int t = blockIdx.x >> 2, grp32 = (blockIdx.x & 3) * 32;

    if (tid < 512) b0s[tid] = bih0[tid] + bhh0[tid];
    {
        float4* xs4 = reinterpret_cast<float4*>(sm1);
        const float4* xf4 = reinterpret_cast<const float4*>(x);
#pragma unroll
        for (int k2 = 0; k2 < 2; k2++) {
            int j = tid + k2 * 1024;
            int m = j >> 6, q = j & 63;
            xs4[m * 64 + q] = __ldg(&xf4[((size_t)(grp32 + m) * T_ + t) * 64 + q]);
        }
    }
    __syncthreads();

    const int s = ws & 7, o = ws >> 3;
    const u64x2* wp = reinterpret_cast<const u64x2*>(gW1i) + (size_t)256 * 256 + s * 32 + lane;
    const u64x2* ax = reinterpret_cast<const u64x2*>(sm1) + (o * 8) * 64;

    u64 acc[8][2];
#pragma unroll
    for (int mi = 0; mi < 8; mi++) { acc[mi][0] = 0; acc[mi][1] = 0; }
    u64x2 pw0 = wp[0], pw1 = wp[256];
#pragma unroll 4
    for (int blk = 0; blk < 64; blk++) {
        u64x2 w0 = pw0, w1 = pw1;
        if (blk < 63) { pw0 = wp[(size_t)(2 * blk + 2) * 256]; pw1 = wp[(size_t)(2 * blk + 3) * 256]; }
#pragma unroll
        for (int mi = 0; mi < 8; mi++) {
            u64x2 a2 = ax[mi * 64 + blk];
            acc[mi][0] = fma2_(a2.x, w0.x, acc[mi][0]);
            acc[mi][1] = fma2_(a2.x, w0.y, acc[mi][1]);
            acc[mi][0] = fma2_(a2.y, w1.x, acc[mi][0]);
            acc[mi][1] = fma2_(a2.y, w1.y, acc[mi][1]);
        }
    }
    const int c0 = s * 64 + 2 * lane;
    float2 bb = *reinterpret_cast<const float2*>(&b0s[c0]);
#pragma unroll
    for (int mi = 0; mi < 8; mi++) {
        float e0, o0, e1, o1;
        unpack2(acc[mi][0], e0, o0); unpack2(acc[mi][1], e1, o1);
        *reinterpret_cast<float2*>(
            &gXP[((size_t)t * 128 + grp32 + o * 8 + mi) * 512 + c0]) =
            make_float2(e0 + o0 + bb.x, e1 + o1 + bb.y);
    }
}

// ---------- pass 3: Y = H2 @ Wout^T + bout ----------
__global__ void __launch_bounds__(512, 1)
rnn_yproj(const float* __restrict__ bout, float* __restrict__ out) {
    extern __shared__ float sm3[];   // hs: 16384 f, bos: 256 f
    float* bos = sm3 + 16384;
    const int tid = threadIdx.x, lane = tid & 31, ws = tid >> 5;
    const size_t r0 = (size_t)blockIdx.x * 32;

    if (tid < 256) bos[tid] = bout[tid];
    {
        float4* hs4 = reinterpret_cast<float4*>(sm3);
        const float4* hf4 = reinterpret_cast<const float4*>(gH2);
#pragma unroll
        for (int k2 = 0; k2 < 8; k2++) {
            int j = tid + k2 * 512;
            int m = j >> 7, q = j & 127;
            hs4[m * 128 + q] = __ldg(&hf4[(r0 + m) * 128 + q]);
        }
    }
    __syncthreads();

    const int s = ws & 3, o = ws >> 2;
    const u64x2* wp = reinterpret_cast<const u64x2*>(gW3i) + s * 32 + lane;
    const u64x2* ah = reinterpret_cast<const u64x2*>(sm3) + (o * 8) * 128;

    u64 acc[8][2];
#pragma unroll
    for (int mi = 0; mi < 8; mi++) { acc[mi][0] = 0; acc[mi][1] = 0; }
    u64x2 pw0 = wp[0], pw1 = wp[128];
#pragma unroll 4
    for (int blk = 0; blk < 128; blk++) {
        u64x2 w0 = pw0, w1 = pw1;
        if (blk < 127) { pw0 = wp[(size_t)(2 * blk + 2) * 128]; pw1 = wp[(size_t)(2 * blk + 3) * 128]; }
#pragma unroll
        for (int mi = 0; mi < 8; mi++) {
            u64x2 a2 = ah[mi * 128 + blk];
            acc[mi][0] = fma2_(a2.x, w0.x, acc[mi][0]);
            acc[mi][1] = fma2_(a2.x, w0.y, acc[mi][1]);
            acc[mi][0] = fma2_(a2.y, w1.x, acc[mi][0]);
            acc[mi][1] = fma2_(a2.y, w1.y, acc[mi][1]);
        }
    }
    const int c0 = s * 64 + 2 * lane;
    float2 bb = *reinterpret_cast<const float2*>(&bos[c0]);
#pragma unroll
    for (int mi = 0; mi < 8; mi++) {
        float e0, o0, e1, o1;
        unpack2(acc[mi][0], e0, o0); unpack2(acc[mi][1], e1, o1);
        *reinterpret_cast<float2*>(&out[(r0 + o * 8 + mi) * 256 + c0]) =
            make_float2(e0 + o0 + bb.x, e1 + o1 + bb.y);
    }
}

// ---------- pass 2 SMEM layout (float offsets) ----------
#define AST_OFF  32768
#define ASB_OFF  36864
#define SCR_OFF  40960
#define BC_OFF   49152
#define MBB_LO   49216
#define MBB_HI   49218
#define MBA_LO   49220
#define MBA_HI   49222
#define SMEM_FLOATS 49224
#define SMEM_BYTES (SMEM_FLOATS * 4)
#define TX_HALF 8192u

// ---------- pass 2: recurrent core (cluster 8, 512 threads, 16 warps) ----------
__global__ void __launch_bounds__(512, 1) __cluster_dims__(8, 1, 1)
rnn_main2(const float* __restrict__ h0, const float* __restrict__ bih1,
          const float* __restrict__ bhh1) {
    extern __shared__ float smem[];
    float* W2S = smem;
    u64*   AST = reinterpret_cast<u64*>(smem + AST_OFF);
    float* SCR = smem + SCR_OFF;
    float* bcs = smem + BC_OFF;

    const int tid  = threadIdx.x;
    const int lane = tid & 31;
    const int ws   = tid >> 5;   // 16-way split-K slice
    const int grp8 = (blockIdx.x >> 3) * 8;
    const int rank = blockIdx.x & 7;
    const int nb = rank * 64;

    uint32_t smem_u32;
    asm("{ .reg .u64 t; cvta.to.shared.u64 t, %1; cvt.u32.u64 %0, t; }"
        : "=r"(smem_u32) : "l"(smem));
    const uint32_t mbBlo = smem_u32 + MBB_LO * 4;
    const uint32_t mbBhi = smem_u32 + MBB_HI * 4;
    const uint32_t mbAlo = smem_u32 + MBA_LO * 4;
    const uint32_t mbAhi = smem_u32 + MBA_HI * 4;

    if (tid < 64) bcs[tid] = bih1[nb + tid] + bhh1[nb + tid];

    for (int i = tid; i < 32768; i += 512) {
        int kp2 = i >> 7, rem = i & 127;
        W2S[i] = gW2i[kp2 * 1024 + rank * 128 + rem];
    }
    {   // stage h0
        const int m = tid >> 6, q = tid & 63;
        float4* f4 = reinterpret_cast<float4*>(AST);
        const float4* hsrc = reinterpret_cast<const float4*>(h0 + (size_t)(grp8 + m) * H_);
        f4[m * 128 + q]      = __ldg(hsrc + q);
        f4[m * 128 + 64 + q] = __ldg(hsrc + q + 64);
    }
    if (tid == 0) {
        mbar_init(mbBlo, 1); mbar_init(mbBhi, 1);
        mbar_init(mbAlo, 1); mbar_init(mbAhi, 1);
        mbar_arm(mbBlo, TX_HALF); mbar_arm(mbBhi, TX_HALF);
    }
    __syncthreads();
    cluster_bar();

    // base pointers
    const u64x2* wA = reinterpret_cast<const u64x2*>(gW1i) + (size_t)(ws * 16) * 256 + rank * 32 + lane;
    const u64x2* aA = reinterpret_cast<const u64x2*>(AST) + ws * 8;
    const u64x2* wB = reinterpret_cast<const u64x2*>(W2S) + ws * 16 * 32 + lane;
    const u64x2* aB = reinterpret_cast<const u64x2*>(smem + ASB_OFF) + ws * 8;

    const int rm = tid >> 5, rc = tid & 31;   // reducers (tid<256)
    const uint32_t dstB = smem_u32 + (uint32_t)(ASB_OFF * 4) + (uint32_t)((rm * 256 + (nb >> 1) + rc) * 8);
    const uint32_t dstA = smem_u32 + (uint32_t)(AST_OFF * 4) + (uint32_t)((rm * 256 + (nb >> 1) + rc) * 8);
    const uint32_t myMbB = (rank < 4) ? mbBlo : mbBhi;
    const uint32_t myMbA = (rank < 4) ? mbAlo : mbAhi;
    const size_t xoff = (size_t)(grp8 + rm) * 512 + nb + 2 * rc;       // + t*65536
    const size_t hoff = (size_t)(grp8 + rm) * T_ * 512 + nb + 2 * rc;  // + t*512

    for (int t = 0; t < T_; t++) {
        const uint32_t pPrev = (uint32_t)((t - 1) & 1);
        const uint32_t pCur  = (uint32_t)(t & 1);

        u64 xp_r = 0;
        if (tid < 256)
            xp_r = *reinterpret_cast<const u64*>(gXP + (size_t)t * 65536 + xoff);

        // ===== Phase A: h1 = tanh(h2 @ Whh0^T + XP[t]) =====
        // depth-4 rolling weight prefetch; all 8 initial LDGs issued BEFORE the wait
        u64x2 w0r[4], w1r[4];
#pragma unroll
        for (int i = 0; i < 4; i++) {
            w0r[i] = wA[(size_t)(2 * i) * 256];
            w1r[i] = wA[(size_t)(2 * i + 1) * 256];
        }
        if (t) { if (ws < 8) mbar_wait(mbAlo, pPrev); else mbar_wait(mbAhi, pPrev); }
        u64 acc[8][2];
#pragma unroll
        for (int m = 0; m < 8; m++) { acc[m][0] = 0; acc[m][1] = 0; }
#pragma unroll
        for (int blk = 0; blk < 8; blk++) {
            const int s = blk & 3;
            u64x2 w0 = w0r[s], w1 = w1r[s];
            if (blk < 4) {
                w0r[s] = wA[(size_t)(2 * blk + 8) * 256];
                w1r[s] = wA[(size_t)(2 * blk + 9) * 256];
            }
#pragma unroll
            for (int m = 0; m < 8; m++) {
                u64x2 a2 = aA[m * 128 + blk];
                acc[m][0] = fma2_(a2.x, w0.x, acc[m][0]);
                acc[m][1] = fma2_(a2.x, w0.y, acc[m][1]);
                acc[m][0] = fma2_(a2.y, w1.x, acc[m][0]);
                acc[m][1] = fma2_(a2.y, w1.y, acc[m][1]);
            }
        }
        __syncthreads();  // (a): AST reads done; prev SCR readers done
#pragma unroll
        for (int m = 0; m < 8; m++) {
            float e0, o0, e1, o1;
            unpack2(acc[m][0], e0, o0); unpack2(acc[m][1], e1, o1);
            *reinterpret_cast<float2*>(&SCR[ws * 512 + m * 64 + 2 * lane]) =
                make_float2(e0 + o0, e1 + o1);
        }
        if (tid == 0) { mbar_arm(mbAlo, TX_HALF); mbar_arm(mbAhi, TX_HALF); }
        __syncthreads();  // (b)
        if (tid < 256) {  // tree-reduce 16-way + XP + tanh -> publish h1 halves
            u64 s = tree_reduce16(SCR + rm * 64 + 2 * rc, 512);
            s = add2_(s, xp_r);
            float e, o; unpack2(s, e, o);
            u64 v = pack2(mytanh(e), mytanh(o));
#pragma unroll
            for (int r = 0; r < 8; r++)
                st_async64(mapa_u32(dstB, r), v, mapa_u32(myMbB, r));
        }

        // ===== Phase B: h2 = tanh(h1 @ Wc^T + bc) =====
        if (ws < 8) mbar_wait(mbBlo, pCur); else mbar_wait(mbBhi, pCur);
#pragma unroll
        for (int m = 0; m < 8; m++) { acc[m][0] = 0; acc[m][1] = 0; }
#pragma unroll
        for (int blk = 0; blk < 8; blk++) {
            u64x2 w0 = wB[(2 * blk) * 32];
            u64x2 w1 = wB[(2 * blk + 1) * 32];
#pragma unroll
            for (int m = 0; m < 8; m++) {
                u64x2 a2 = aB[m * 128 + blk];
                acc[m][0] = fma2_(a2.x, w0.x, acc[m][0]);
                acc[m][1] = fma2_(a2.x, w0.y, acc[m][1]);
                acc[m][0] = fma2_(a2.y, w1.x, acc[m][0]);
                acc[m][1] = fma2_(a2.y, w1.y, acc[m][1]);
            }
        }
        __syncthreads();  // (c): SCR readers (h1-reduce) done
#pragma unroll
        for (int m = 0; m < 8; m++) {
            float e0, o0, e1, o1;
            unpack2(acc[m][0], e0, o0); unpack2(acc[m][1], e1, o1);
            *reinterpret_cast<float2*>(&SCR[ws * 512 + m * 64 + 2 * lane]) =
                make_float2(e0 + o0, e1 + o1);
        }
        if (tid == 0) { mbar_arm(mbBlo, TX_HALF); mbar_arm(mbBhi, TX_HALF); }  // for t+1
        __syncthreads();  // (d)
        if (tid < 256) {  // tree-reduce + tanh -> publish h2 + store H2
            u64 s = tree_reduce16(SCR + rm * 64 + 2 * rc, 512);
            s = add2_(s, *reinterpret_cast<const u64*>(bcs + 2 * rc));
            float e, o; unpack2(s, e, o);
            u64 v = pack2(mytanh(e), mytanh(o));
#pragma unroll
            for (int r = 0; r < 8; r++)
                st_async64(mapa_u32(dstA, r), v, mapa_u32(myMbA, r));
            *reinterpret_cast<u64*>(&gH2[hoff + (size_t)t * 512]) = v;
        }
    }
    // drain final h2 exchange, then keep SMEM alive until cluster traffic retires
    mbar_wait(mbAlo, (uint32_t)((T_ - 1) & 1));
    mbar_wait(mbAhi, (uint32_t)((T_ - 1) & 1));
    cluster_bar();
}

extern "C" void kernel_launch(void* const* d_in, const int* in_sizes, int n_in,
                              void* d_out, int out_size) {
    const float* x    = (const float*)d_in[0];
    const float* h0   = (const float*)d_in[1];
    const float* Wih0 = (const float*)d_in[2];
    const float* bih0 = (const float*)d_in[3];
    const float* Whh0 = (const float*)d_in[4];
    const float* bhh0 = (const float*)d_in[5];
    const float* Wih1 = (const float*)d_in[6];
    const float* bih1 = (const float*)d_in[7];
    const float* Whh1 = (const float*)d_in[8];
    const float* bhh1 = (const float*)d_in[9];
    const float* Wout = (const float*)d_in[10];
    const float* bout = (const float*)d_in[11];
    float* out = (float*)d_out;

    cudaFuncSetAttribute(rnn_main2, cudaFuncAttributeMaxDynamicSharedMemorySize, SMEM_BYTES);
    cudaFuncSetAttribute(rnn_yproj, cudaFuncAttributeMaxDynamicSharedMemorySize, (16384 + 256) * 4);

    rnn_prep<<<1536, 256>>>(Wih0, Whh0, Wih1, Whh1, Wout);
    rnn_xproj<<<4096, 1024, (8192 + 512) * 4>>>(x, bih0, bhh0);
    rnn_main2<<<128, 512, SMEM_BYTES>>>(h0, bih1, bhh1);
    rnn_yproj<<<4096, 512, (16384 + 256) * 4>>>(bout, out);
}